// round 16
// baseline (speedup 1.0000x reference)
#include <cuda_runtime.h>
#include <cuda_bf16.h>
#include <cuda_fp16.h>
#include <math.h>
#include <stdint.h>

#define B_  512
#define S_  512
#define DI_ 256
#define DO_ 256

// fp16 fragment-packed weights: [g(=t*8+chunk)][w(8)][s2(2)][mt(2)][lane(32)] float4 (=8 f16)
__device__ float4 WhP_h[(size_t)S_ * 8 * 8 * 128];   // 67 MB
__device__ float4 WxP_h[(size_t)S_ * 8 * 8 * 128];   // 67 MB
__device__ int flagZ_g[S_];                          // 8 tiles per t

// ---------------- helpers ----------------

__device__ __forceinline__ unsigned f2u(float f) { return __float_as_uint(f); }
__device__ __forceinline__ float fast_tanh(float x) {
    float e = __expf(2.0f * x);
    return 1.0f - __fdividef(2.0f, e + 1.0f);
}
__device__ __forceinline__ uint32_t smem_u32(const void* p) {
    return (uint32_t)__cvta_generic_to_shared(p);
}
__device__ __forceinline__ uint32_t packh2(float a, float b) {
    __half2 h = __floats2half2_rn(a, b);
    return *(uint32_t*)&h;
}
__device__ __forceinline__ int ld_acquire(const int* p) {
    int v;
    asm volatile("ld.acquire.gpu.global.s32 %0, [%1];" : "=r"(v) : "l"(p) : "memory");
    return v;
}
__device__ __forceinline__ void red_release_add(int* p, int v) {
    asm volatile("red.release.gpu.global.add.s32 [%0], %1;" :: "l"(p), "r"(v) : "memory");
}

__device__ __forceinline__ void mma_f16(float c[4],
                                        unsigned a0, unsigned a1, unsigned a2, unsigned a3,
                                        unsigned b0, unsigned b1) {
    asm volatile(
        "mma.sync.aligned.m16n8k16.row.col.f32.f16.f16.f32 "
        "{%0,%1,%2,%3}, {%4,%5,%6,%7}, {%8,%9}, {%0,%1,%2,%3};\n"
        : "+f"(c[0]), "+f"(c[1]), "+f"(c[2]), "+f"(c[3])
        : "r"(a0), "r"(a1), "r"(a2), "r"(a3), "r"(b0), "r"(b1));
}

#define LDSM_X4(r0, r1, r2, r3, addr) \
    asm volatile("ldmatrix.sync.aligned.m8n8.x4.shared.b16 {%0,%1,%2,%3}, [%4];" \
                 : "=r"(r0), "=r"(r1), "=r"(r2), "=r"(r3) : "r"(addr))

#define NBAR64(id)  asm volatile("bar.sync %0, 64;"  :: "r"(id) : "memory")
#define NBAR256(id) asm volatile("bar.sync %0, 256;" :: "r"(id) : "memory")

// ---------------- Prepack W (both weights) -> fp16 fragments + zero flags ----------------

__global__ __launch_bounds__(256, 1) void prepack_w(const float* __restrict__ Wh,
                                                    const float* __restrict__ Wx)
{
    __shared__ float tile[32 * 260];
    const int slab = blockIdx.x;
    const int t    = blockIdx.y;
    const int tid  = threadIdx.x;
    const float* W = blockIdx.z ? Wx : Wh;
    float4* dst    = blockIdx.z ? WxP_h : WhP_h;

    if (slab == 0 && t == 0 && blockIdx.z == 0) {
        for (int i = tid; i < S_; i += 256) flagZ_g[i] = 0;
    }

    const float* src = W + (size_t)t * (DO_ * DO_) + (size_t)slab * 32 * DO_;
#pragma unroll
    for (int j = 0; j < 8; j++) {
        int idx = tid + j * 256;
        int r = idx >> 6, q = idx & 63;
        *(float4*)&tile[r * 260 + q * 4] = *(const float4*)&src[r * DO_ + q * 4];
    }
    __syncthreads();

    const size_t g = (size_t)t * 8 + slab;
#pragma unroll
    for (int j = 0; j < 4; j++) {
        int idx  = tid + j * 256;
        int lane = idx & 31;
        int mt   = (idx >> 5) & 1;
        int s2   = (idx >> 6) & 1;
        int wm   = (idx >> 7) & 7;
        int r    = lane >> 2, cc = (lane & 3) * 2;
        int m0   = wm * 32 + mt * 16 + r;
        int kk   = s2 * 16 + cc;
        float4 v;
        v.x = __uint_as_float(packh2(tile[kk * 260 + m0],       tile[(kk + 1) * 260 + m0]));
        v.y = __uint_as_float(packh2(tile[kk * 260 + m0 + 8],   tile[(kk + 1) * 260 + m0 + 8]));
        v.z = __uint_as_float(packh2(tile[(kk + 8) * 260 + m0], tile[(kk + 9) * 260 + m0]));
        v.w = __uint_as_float(packh2(tile[(kk + 8) * 260 + m0 + 8], tile[(kk + 9) * 260 + m0 + 8]));
        dst[(g * 8 + wm) * 128 + (s2 * 2 + mt) * 32 + lane] = v;
    }
}

// ---------------- Fused: fp16 half-CTA phase-1 workers + phase-2 consumers ----------------

#define P1_XSTR 264
#define P1_ZSTR 260
#define HALF_SMEMB (64 * P1_ZSTR * 4)        // 66,560 B per half-worker
#define FK_SMEM (2 * HALF_SMEMB)             // 133,120 B
#define P2_HSTR 264

__global__ __launch_bounds__(512, 1) void rnn_fused(
    const float* __restrict__ x, float* __restrict__ out)
{
    extern __shared__ float smf[];
    const int tid = threadIdx.x;

    if (blockIdx.x >= 64) {
        // ---------------- phase-1 half-workers (R15 tile, named barriers) ----------------
        const int hg    = tid >> 8;
        const int wtid  = tid & 255;
        const int barid = hg + 1;
        const int w     = wtid >> 5, lane = wtid & 31;
        const int grp   = lane >> 2, tig = lane & 3;

        float*  zsf = smf + hg * (HALF_SMEMB / 4);
        __half* xs  = (__half*)zsf;

        const int hw  = (blockIdx.x - 64) * 2 + hg;
        const int nhw = (gridDim.x - 64) * 2;

        for (int tile = hw; tile < 8 * S_; tile += nhw) {
            const int t     = tile >> 3;
            const int btile = tile & 7;

            float4 A[2][2][2];
            auto ldA = [&](int c, int st) {
                const size_t base = (((size_t)t * 8 + c) * 8 + w) * 128 + lane;
                A[st][0][0] = __ldg(&WxP_h[base]);
                A[st][0][1] = __ldg(&WxP_h[base + 32]);
                A[st][1][0] = __ldg(&WxP_h[base + 64]);
                A[st][1][1] = __ldg(&WxP_h[base + 96]);
            };
            ldA(0, 0);
            ldA(1, 1);

            // x tile: f32 load -> fp16 convert -> STS
#pragma unroll
            for (int j = 0; j < 16; j++) {
                int i = wtid + j * 256;
                int r = i >> 6, q = i & 63;
                float4 v = __ldg((const float4*)&x[((size_t)(btile * 64 + r) * S_ + t) * DI_ + q * 4]);
                uint2 o;
                o.x = packh2(v.x, v.y);
                o.y = packh2(v.z, v.w);
                *(uint2*)&xs[r * P1_XSTR + q * 4] = o;
            }

            float acc[2][8][4];
#pragma unroll
            for (int mt = 0; mt < 2; mt++)
#pragma unroll
                for (int ng = 0; ng < 8; ng++)
#pragma unroll
                    for (int i = 0; i < 4; i++) acc[mt][ng][i] = 0.f;

            NBAR256(barid);

            const uint32_t xs_base = smem_u32(xs);
            const uint32_t lmb = xs_base + (uint32_t)(lane & 7) * (P1_XSTR * 2) + (uint32_t)(lane >> 3) * 16;

#pragma unroll
            for (int c = 0; c < 8; c++) {
#pragma unroll
                for (int ng = 0; ng < 8; ng++) {
                    uint32_t b0, b1, b2, b3;
                    LDSM_X4(b0, b1, b2, b3, lmb + (uint32_t)ng * (8 * P1_XSTR * 2) + (uint32_t)c * 64);
                    {
                        const float4 a0 = A[c & 1][0][0];
                        mma_f16(acc[0][ng], f2u(a0.x), f2u(a0.y), f2u(a0.z), f2u(a0.w), b0, b1);
                        const float4 a1 = A[c & 1][0][1];
                        mma_f16(acc[1][ng], f2u(a1.x), f2u(a1.y), f2u(a1.z), f2u(a1.w), b0, b1);
                    }
                    {
                        const float4 a0 = A[c & 1][1][0];
                        mma_f16(acc[0][ng], f2u(a0.x), f2u(a0.y), f2u(a0.z), f2u(a0.w), b2, b3);
                        const float4 a1 = A[c & 1][1][1];
                        mma_f16(acc[1][ng], f2u(a1.x), f2u(a1.y), f2u(a1.z), f2u(a1.w), b2, b3);
                    }
                }
                if (c + 2 < 8) ldA(c + 2, c & 1);
            }

            NBAR256(barid);   // all LDSM reads done; zs may overwrite xs

#pragma unroll
            for (int mt = 0; mt < 2; mt++) {
                const int col = w * 32 + mt * 16 + grp;
#pragma unroll
                for (int ng = 0; ng < 8; ng++) {
                    const int r0 = ng * 8 + 2 * tig;
                    zsf[r0 * P1_ZSTR + col]           = acc[mt][ng][0];
                    zsf[(r0 + 1) * P1_ZSTR + col]     = acc[mt][ng][1];
                    zsf[r0 * P1_ZSTR + col + 8]       = acc[mt][ng][2];
                    zsf[(r0 + 1) * P1_ZSTR + col + 8] = acc[mt][ng][3];
                }
            }
            NBAR256(barid);

            const int rl = lane >> 4;
            const int c4 = (lane & 15) * 4;
#pragma unroll
            for (int it = 0; it < 4; it++) {
                const int row = w * 8 + it * 2 + rl;
                const size_t ob = ((size_t)(btile * 64 + row) * S_ + t) * DO_;
#pragma unroll
                for (int q = 0; q < 4; q++) {
                    float4 v = *(float4*)&zsf[row * P1_ZSTR + q * 64 + c4];
                    *(float4*)&out[ob + q * 64 + c4] = v;
                }
            }

            __threadfence();
            NBAR256(barid);
            if (wtid == 0) red_release_add(&flagZ_g[t], 1);
        }
        return;
    }

    // ---------------- phase-2 consumer (R15 verbatim + flag gating) ----------------
    __half* hs2 = (__half*)smf;                                    // 4224 B
    float4 (*scr)[8][32] = (float4(*)[8][32])((char*)smf + 4224);  // 8192 B

    const int w    = tid >> 5, lane = tid & 31;
    const int grp  = lane >> 2, tig = lane & 3;
    const int kh   = w >> 3, wm = w & 7;
    const int brow = blockIdx.x * 8;
    const int m0   = wm * 32 + kh * 16 + grp;
    const int n0   = 2 * tig;

    for (int i = tid; i < 8 * P2_HSTR / 2; i += 512) ((uint32_t*)hs2)[i] = 0u;

    const uint32_t hs_base = smem_u32(hs2);
    const uint32_t lmb = hs_base + (uint32_t)(lane & 7) * (P2_HSTR * 2) + (uint32_t)(lane >> 3) * 16;

    float4 A[2][2][2];
    auto ldA = [&](int s, int st) {
        const int g = ((s >> 2) << 3) | (kh << 2) | (s & 3);
        const size_t base = ((size_t)g * 8 + wm) * 128 + lane;
        A[st][0][0] = __ldg(&WhP_h[base]);
        A[st][0][1] = __ldg(&WhP_h[base + 32]);
        A[st][1][0] = __ldg(&WhP_h[base + 64]);
        A[st][1][1] = __ldg(&WhP_h[base + 96]);
    };
    ldA(0, 0);
    ldA(1, 1);

    if (tid == 0) {
        while (ld_acquire(&flagZ_g[0]) < 8) __nanosleep(64);
    }
    __syncthreads();

    float acc[2][4];
    float z[4];
    int s = 0;

    for (int t = 0; t < S_; t++) {
#pragma unroll
        for (int mt = 0; mt < 2; mt++)
#pragma unroll
            for (int i = 0; i < 4; i++) acc[mt][i] = 0.f;

        z[0] = out[((size_t)(brow + n0)     * S_ + t) * DO_ + m0];
        z[1] = out[((size_t)(brow + n0 + 1) * S_ + t) * DO_ + m0];
        z[2] = out[((size_t)(brow + n0)     * S_ + t) * DO_ + m0 + 8];
        z[3] = out[((size_t)(brow + n0 + 1) * S_ + t) * DO_ + m0 + 8];

        for (int c = 0; c < 4; c++) {
            const int st = s & 1;
            const int k0 = kh * 128 + c * 32;
            uint32_t b0, b1, b2, b3;
            LDSM_X4(b0, b1, b2, b3, lmb + (uint32_t)k0 * 2);
            {
                const float4 af0 = A[st][0][0];
                mma_f16(acc[0], f2u(af0.x), f2u(af0.y), f2u(af0.z), f2u(af0.w), b0, b1);
                const float4 af1 = A[st][0][1];
                mma_f16(acc[1], f2u(af1.x), f2u(af1.y), f2u(af1.z), f2u(af1.w), b0, b1);
            }
            {
                const float4 af0 = A[st][1][0];
                mma_f16(acc[0], f2u(af0.x), f2u(af0.y), f2u(af0.z), f2u(af0.w), b2, b3);
                const float4 af1 = A[st][1][1];
                mma_f16(acc[1], f2u(af1.x), f2u(af1.y), f2u(af1.z), f2u(af1.w), b2, b3);
            }
            if (s + 2 < 4 * S_) ldA(s + 2, st);
            s++;
        }

        if (kh == 0) {
            (*scr)[wm][lane] = make_float4(acc[1][0], acc[1][1], acc[1][2], acc[1][3]);
        } else {
            scr[1][wm][lane] = make_float4(acc[0][0], acc[0][1], acc[0][2], acc[0][3]);
        }
        NBAR64(wm + 1);

        const float4 p = scr[kh ^ 1][wm][lane];
        const float h0 = fast_tanh(z[0] + acc[kh][0] + p.x);
        const float h1 = fast_tanh(z[1] + acc[kh][1] + p.y);
        const float h2 = fast_tanh(z[2] + acc[kh][2] + p.z);
        const float h3 = fast_tanh(z[3] + acc[kh][3] + p.w);

        out[((size_t)(brow + n0)     * S_ + t) * DO_ + m0]     = h0;
        out[((size_t)(brow + n0 + 1) * S_ + t) * DO_ + m0]     = h1;
        out[((size_t)(brow + n0)     * S_ + t) * DO_ + m0 + 8] = h2;
        out[((size_t)(brow + n0 + 1) * S_ + t) * DO_ + m0 + 8] = h3;

        hs2[n0 * P2_HSTR + m0]           = __float2half_rn(h0);
        hs2[(n0 + 1) * P2_HSTR + m0]     = __float2half_rn(h1);
        hs2[n0 * P2_HSTR + m0 + 8]       = __float2half_rn(h2);
        hs2[(n0 + 1) * P2_HSTR + m0 + 8] = __float2half_rn(h3);

        if (tid == 0 && t + 1 < S_) {
            while (ld_acquire(&flagZ_g[t + 1]) < 8) __nanosleep(64);
        }
        __syncthreads();
    }
}

// ---------------- launch ----------------

extern "C" void kernel_launch(void* const* d_in, const int* in_sizes, int n_in,
                              void* d_out, int out_size)
{
    const float* x  = (const float*)d_in[0];   // [B, S, DI]
    const float* Wx = (const float*)d_in[1];   // [S, DI, DO]
    const float* Wh = (const float*)d_in[2];   // [S, DO, DO]
    float* out = (float*)d_out;                // [B, S, DO]

    int nsm = 148;
    cudaDeviceGetAttribute(&nsm, cudaDevAttrMultiProcessorCount, 0);

    cudaFuncSetAttribute(rnn_fused, cudaFuncAttributeMaxDynamicSharedMemorySize, FK_SMEM);

    prepack_w<<<dim3(8, S_, 2), 256>>>(Wh, Wx);
    rnn_fused<<<nsm, 512, FK_SMEM>>>(x, out);
}